// round 5
// baseline (speedup 1.0000x reference)
#include <cuda_runtime.h>
#include <cuda_fp16.h>
#include <cstdint>

// Problem constants (fixed by the dataset)
#define NI 32
#define H  128
#define NC 64

// Fragment-buffer geometry.
// Weights are stored as m16n8k16 B-fragments, K-pair-packed into uint4:
//   uint4 = { b0(kt=2kp), b1(kt=2kp), b0(kt=2kp+1), b1(kt=2kp+1) }
//   b0 = half2{ B[k0][n], B[k0+1][n] },  k0 = kt*16 + (lane%4)*2,  n = nt*8 + lane/4
//   b1 = same with k0+8
#define NFRAG_CAT (16*3*32)   // Wcat: K=96 (x|cond), N=128  -> 1536 uint4
#define NFRAG_W2  (16*4*32)   // W2:   K=128, N=128          -> 2048 uint4
#define NFRAG_W3  (8*4*32)    // W3:   K=128, N=64           -> 1024 uint4
#define NFRAG_TOT (NFRAG_CAT + NFRAG_W2 + NFRAG_W3)          // 4608 uint4 = 73728 B
#define SMEM_BYTES (NFRAG_TOT*16 + (H + H + 2*NI)*4)         // + biases = 75008 B

__device__ uint4 g_wfrags[NFRAG_TOT];

static __device__ __forceinline__ unsigned pack2(float a, float b) {
    __half2 h = __floats2half2_rn(a, b);
    return *reinterpret_cast<unsigned*>(&h);
}

// ---------------------------------------------------------------------------
// Pre-pack kernel: apply MADE masks, convert to f16, write fragment order.
// deg_hid[h] = h % 31 ; deg_in[i] = i ; deg_out[o] = o % 32 - 1
// Layer1 B[k][n]: k<32 -> W1[n][k] * (n%31 >= k) ; k>=32 -> Wc[n][k-32]
// Layer2 B[k][n]: W2[n][k] * (n%31 >= k%31)
// Layer3 B[k][n]: W3[n][k] * ((n%32 - 1) >= k%31)
// ---------------------------------------------------------------------------
__global__ void made_prep(const float* __restrict__ W1, const float* __restrict__ Wc,
                          const float* __restrict__ W2, const float* __restrict__ W3) {
    int idx = blockIdx.x * blockDim.x + threadIdx.x;
    if (idx >= NFRAG_TOT) return;
    int mat, base, KP;
    if (idx < NFRAG_CAT)                { mat = 0; base = idx;                       KP = 3; }
    else if (idx < NFRAG_CAT+NFRAG_W2)  { mat = 1; base = idx - NFRAG_CAT;           KP = 4; }
    else                                { mat = 2; base = idx - (NFRAG_CAT+NFRAG_W2); KP = 4; }
    int lane = base & 31;
    int kp   = (base >> 5) % KP;
    int nt   = (base >> 5) / KP;
    int t = lane & 3, g = lane >> 2;
    int n = nt * 8 + g;

    float e[8];
#pragma unroll
    for (int i = 0; i < 8; i++) {
        int regsel = i >> 1;                       // 0..3: b0/b1 of kt-even, b0/b1 of kt-odd
        int kt = 2*kp + (regsel >> 1);
        int k  = kt*16 + (regsel & 1)*8 + 2*t + (i & 1);
        float v;
        if (mat == 0) {
            if (k < NI) v = ((n % 31) >= k) ? W1[n*NI + k] : 0.f;
            else        v = Wc[n*NC + (k - NI)];
        } else if (mat == 1) {
            v = ((n % 31) >= (k % 31)) ? W2[n*H + k] : 0.f;
        } else {
            v = (((n % 32) - 1) >= (k % 31)) ? W3[n*H + k] : 0.f;
        }
        e[i] = v;
    }
    uint4 r;
    r.x = pack2(e[0], e[1]);
    r.y = pack2(e[2], e[3]);
    r.z = pack2(e[4], e[5]);
    r.w = pack2(e[6], e[7]);
    g_wfrags[idx] = r;
}

// ---------------------------------------------------------------------------
// Main fused kernel
// ---------------------------------------------------------------------------
__device__ __forceinline__ void mma16816(float c[4], const unsigned a[4],
                                         unsigned b0, unsigned b1) {
    asm("mma.sync.aligned.m16n8k16.row.col.f32.f16.f16.f32 "
        "{%0,%1,%2,%3}, {%4,%5,%6,%7}, {%8,%9}, {%0,%1,%2,%3};"
        : "+f"(c[0]), "+f"(c[1]), "+f"(c[2]), "+f"(c[3])
        : "r"(a[0]), "r"(a[1]), "r"(a[2]), "r"(a[3]), "r"(b0), "r"(b1));
}

#define WARPS 4
#define NITER 8
#define ROWS_PER_CTA (WARPS*NITER*16)   // 512 samples per CTA

__global__ __launch_bounds__(128, 1)
void made_main(const float* __restrict__ x, const float* __restrict__ cond,
               const float* __restrict__ b1, const float* __restrict__ b2,
               const float* __restrict__ b3,
               float* __restrict__ out_u, float* __restrict__ out_ld) {
    extern __shared__ unsigned char smem_raw[];
    uint4* sW  = (uint4*)smem_raw;
    float* sb1 = (float*)(sW + NFRAG_TOT);
    float* sb2 = sb1 + H;
    float* sb3 = sb2 + H;

    for (int i = threadIdx.x; i < NFRAG_TOT; i += blockDim.x) sW[i] = g_wfrags[i];
    if (threadIdx.x < H)    { sb1[threadIdx.x] = b1[threadIdx.x];
                              sb2[threadIdx.x] = b2[threadIdx.x]; }
    if (threadIdx.x < 2*NI)   sb3[threadIdx.x] = b3[threadIdx.x];
    __syncthreads();

    const uint4* sWcat = sW;
    const uint4* sW2f  = sW + NFRAG_CAT;
    const uint4* sW3f  = sW + NFRAG_CAT + NFRAG_W2;

    int warp = threadIdx.x >> 5;
    int lane = threadIdx.x & 31;
    int g = lane >> 2, t = lane & 3;
    long long base = (long long)blockIdx.x * ROWS_PER_CTA;

    for (int it = 0; it < NITER; ++it) {
        long long m0 = base + (long long)(warp*NITER + it) * 16;
        const float* xb = x    + m0 * NI;
        const float* cb = cond + m0 * NC;

        // ---- Load A1 fragments (x | cond), stash fp32 x for epilogue ----
        unsigned a1[6][4];
        float xs[16];
#pragma unroll
        for (int kt = 0; kt < 2; ++kt)
#pragma unroll
            for (int p = 0; p < 4; ++p) {
                int row = g + (p & 1) * 8;
                int col = kt*16 + 2*t + (p >> 1) * 8;
                float2 v = *(const float2*)(xb + row*NI + col);
                a1[kt][p] = pack2(v.x, v.y);
                int nt = kt*2 + (p >> 1);
                xs[nt*4 + (p & 1)*2 + 0] = v.x;
                xs[nt*4 + (p & 1)*2 + 1] = v.y;
            }
#pragma unroll
        for (int kt = 2; kt < 6; ++kt)
#pragma unroll
            for (int p = 0; p < 4; ++p) {
                int row = g + (p & 1) * 8;
                int col = (kt-2)*16 + 2*t + (p >> 1) * 8;
                float2 v = *(const float2*)(cb + row*NC + col);
                a1[kt][p] = pack2(v.x, v.y);
            }

        // ---- Layer 1: h1 = [x|cond] @ Wcat + b1 ----
        float acc[16][4];
#pragma unroll
        for (int nt = 0; nt < 16; ++nt) {
            float f0 = sb1[nt*8 + 2*t], f1 = sb1[nt*8 + 2*t + 1];
            acc[nt][0] = f0; acc[nt][1] = f1; acc[nt][2] = f0; acc[nt][3] = f1;
        }
#pragma unroll
        for (int nt = 0; nt < 16; ++nt)
#pragma unroll
            for (int kp = 0; kp < 3; ++kp) {
                uint4 w = sWcat[(nt*3 + kp)*32 + lane];
                mma16816(acc[nt], a1[2*kp],   w.x, w.y);
                mma16816(acc[nt], a1[2*kp+1], w.z, w.w);
            }

        // ---- relu + repack accumulators as A fragments (layout identity) ----
        unsigned af[8][4];
#pragma unroll
        for (int kt = 0; kt < 8; ++kt) {
            af[kt][0] = pack2(fmaxf(acc[2*kt][0],  0.f), fmaxf(acc[2*kt][1],  0.f));
            af[kt][1] = pack2(fmaxf(acc[2*kt][2],  0.f), fmaxf(acc[2*kt][3],  0.f));
            af[kt][2] = pack2(fmaxf(acc[2*kt+1][0],0.f), fmaxf(acc[2*kt+1][1],0.f));
            af[kt][3] = pack2(fmaxf(acc[2*kt+1][2],0.f), fmaxf(acc[2*kt+1][3],0.f));
        }

        // ---- Layer 2: h2 = relu(h1 @ W2m + b2) ----
#pragma unroll
        for (int nt = 0; nt < 16; ++nt) {
            float f0 = sb2[nt*8 + 2*t], f1 = sb2[nt*8 + 2*t + 1];
            acc[nt][0] = f0; acc[nt][1] = f1; acc[nt][2] = f0; acc[nt][3] = f1;
        }
#pragma unroll
        for (int nt = 0; nt < 16; ++nt)
#pragma unroll
            for (int kp = 0; kp < 4; ++kp) {
                uint4 w = sW2f[(nt*4 + kp)*32 + lane];
                mma16816(acc[nt], af[2*kp],   w.x, w.y);
                mma16816(acc[nt], af[2*kp+1], w.z, w.w);
            }

#pragma unroll
        for (int kt = 0; kt < 8; ++kt) {
            unsigned v0 = pack2(fmaxf(acc[2*kt][0],  0.f), fmaxf(acc[2*kt][1],  0.f));
            unsigned v1 = pack2(fmaxf(acc[2*kt][2],  0.f), fmaxf(acc[2*kt][3],  0.f));
            unsigned v2 = pack2(fmaxf(acc[2*kt+1][0],0.f), fmaxf(acc[2*kt+1][1],0.f));
            unsigned v3 = pack2(fmaxf(acc[2*kt+1][2],0.f), fmaxf(acc[2*kt+1][3],0.f));
            af[kt][0] = v0; af[kt][1] = v1; af[kt][2] = v2; af[kt][3] = v3;
        }

        // ---- Layer 3: o = h2 @ W3m + b3  (N = 64, tiles 0..3 = m, 4..7 = a) ----
#pragma unroll
        for (int nt = 0; nt < 8; ++nt) {
            float f0 = sb3[nt*8 + 2*t], f1 = sb3[nt*8 + 2*t + 1];
            acc[nt][0] = f0; acc[nt][1] = f1; acc[nt][2] = f0; acc[nt][3] = f1;
        }
#pragma unroll
        for (int nt = 0; nt < 8; ++nt)
#pragma unroll
            for (int kp = 0; kp < 4; ++kp) {
                uint4 w = sW3f[(nt*4 + kp)*32 + lane];
                mma16816(acc[nt], af[2*kp],   w.x, w.y);
                mma16816(acc[nt], af[2*kp+1], w.z, w.w);
            }

        // ---- Epilogue: a=clip(a,-5,5); u=(x-m)*exp(-a); logdet=-sum(a) ----
        float sa0 = 0.f, sa1 = 0.f;
#pragma unroll
        for (int nt = 0; nt < 4; ++nt) {
            float a00 = fminf(fmaxf(acc[nt+4][0], -5.f), 5.f);
            float a01 = fminf(fmaxf(acc[nt+4][1], -5.f), 5.f);
            float a10 = fminf(fmaxf(acc[nt+4][2], -5.f), 5.f);
            float a11 = fminf(fmaxf(acc[nt+4][3], -5.f), 5.f);
            float u00 = (xs[nt*4+0] - acc[nt][0]) * __expf(-a00);
            float u01 = (xs[nt*4+1] - acc[nt][1]) * __expf(-a01);
            float u10 = (xs[nt*4+2] - acc[nt][2]) * __expf(-a10);
            float u11 = (xs[nt*4+3] - acc[nt][3]) * __expf(-a11);
            float2 w0; w0.x = u00; w0.y = u01;
            float2 w1; w1.x = u10; w1.y = u11;
            *(float2*)(out_u + (m0 + g    )*NI + nt*8 + 2*t) = w0;
            *(float2*)(out_u + (m0 + g + 8)*NI + nt*8 + 2*t) = w1;
            sa0 += a00 + a01;
            sa1 += a10 + a11;
        }
        sa0 += __shfl_xor_sync(0xffffffffu, sa0, 1);
        sa0 += __shfl_xor_sync(0xffffffffu, sa0, 2);
        sa1 += __shfl_xor_sync(0xffffffffu, sa1, 1);
        sa1 += __shfl_xor_sync(0xffffffffu, sa1, 2);
        if (t == 0) {
            out_ld[m0 + g]     = -sa0;
            out_ld[m0 + g + 8] = -sa1;
        }
    }
}

// ---------------------------------------------------------------------------
// Launch
// ---------------------------------------------------------------------------
extern "C" void kernel_launch(void* const* d_in, const int* in_sizes, int n_in,
                              void* d_out, int out_size) {
    const float* x    = (const float*)d_in[0];
    const float* cond = (const float*)d_in[1];
    const float* W1   = (const float*)d_in[2];
    const float* b1   = (const float*)d_in[3];
    const float* Wc   = (const float*)d_in[4];
    const float* W2   = (const float*)d_in[5];
    const float* b2   = (const float*)d_in[6];
    const float* W3   = (const float*)d_in[7];
    const float* b3   = (const float*)d_in[8];

    long long B = (long long)in_sizes[0] / NI;
    float* out_u  = (float*)d_out;
    float* out_ld = out_u + B * NI;

    // Pre-pack masked weights into fragment order (tiny kernel, same stream)
    made_prep<<<(NFRAG_TOT + 127) / 128, 128>>>(W1, Wc, W2, W3);

    cudaFuncSetAttribute(made_main, cudaFuncAttributeMaxDynamicSharedMemorySize,
                         SMEM_BYTES);

    int nCTA = (int)(B / ROWS_PER_CTA);
    made_main<<<nCTA, 128, SMEM_BYTES>>>(x, cond, b1, b2, b3, out_u, out_ld);
}

// round 6
// speedup vs baseline: 1.0013x; 1.0013x over previous
#include <cuda_runtime.h>
#include <cuda_fp16.h>
#include <cstdint>

// Problem constants (fixed by the dataset)
#define NI 32
#define H  128
#define NC 64

// Fragment-buffer geometry.
// Weights are stored as m16n8k16 B-fragments, K-pair-packed into uint4:
//   uint4 = { b0(kt=2kp), b1(kt=2kp), b0(kt=2kp+1), b1(kt=2kp+1) }
//   b0 = half2{ B[k0][n], B[k0+1][n] },  k0 = kt*16 + (lane%4)*2,  n = nt*8 + lane/4
//   b1 = same with k0+8
#define NFRAG_CAT (16*3*32)   // Wcat: K=96 (x|cond), N=128  -> 1536 uint4
#define NFRAG_W2  (16*4*32)   // W2:   K=128, N=128          -> 2048 uint4
#define NFRAG_W3  (8*4*32)    // W3:   K=128, N=64           -> 1024 uint4
#define NFRAG_TOT (NFRAG_CAT + NFRAG_W2 + NFRAG_W3)          // 4608 uint4 = 73728 B
#define SMEM_BYTES (NFRAG_TOT*16 + (H + H + 2*NI)*4)         // + biases = 75008 B

__device__ uint4 g_wfrags[NFRAG_TOT];

static __device__ __forceinline__ unsigned pack2(float a, float b) {
    __half2 h = __floats2half2_rn(a, b);
    return *reinterpret_cast<unsigned*>(&h);
}

// ---------------------------------------------------------------------------
// Pre-pack kernel: apply MADE masks, convert to f16, write fragment order.
// deg_hid[h] = h % 31 ; deg_in[i] = i ; deg_out[o] = o % 32 - 1
// Layer1 B[k][n]: k<32 -> W1[n][k] * (n%31 >= k) ; k>=32 -> Wc[n][k-32]
// Layer2 B[k][n]: W2[n][k] * (n%31 >= k%31)
// Layer3 B[k][n]: W3[n][k] * ((n%32 - 1) >= k%31)
// ---------------------------------------------------------------------------
__global__ void made_prep(const float* __restrict__ W1, const float* __restrict__ Wc,
                          const float* __restrict__ W2, const float* __restrict__ W3) {
    int idx = blockIdx.x * blockDim.x + threadIdx.x;
    if (idx >= NFRAG_TOT) return;
    int mat, base, KP;
    if (idx < NFRAG_CAT)                { mat = 0; base = idx;                       KP = 3; }
    else if (idx < NFRAG_CAT+NFRAG_W2)  { mat = 1; base = idx - NFRAG_CAT;           KP = 4; }
    else                                { mat = 2; base = idx - (NFRAG_CAT+NFRAG_W2); KP = 4; }
    int lane = base & 31;
    int kp   = (base >> 5) % KP;
    int nt   = (base >> 5) / KP;
    int t = lane & 3, g = lane >> 2;
    int n = nt * 8 + g;

    float e[8];
#pragma unroll
    for (int i = 0; i < 8; i++) {
        int regsel = i >> 1;                       // 0..3: b0/b1 of kt-even, b0/b1 of kt-odd
        int kt = 2*kp + (regsel >> 1);
        int k  = kt*16 + (regsel & 1)*8 + 2*t + (i & 1);
        float v;
        if (mat == 0) {
            if (k < NI) v = ((n % 31) >= k) ? W1[n*NI + k] : 0.f;
            else        v = Wc[n*NC + (k - NI)];
        } else if (mat == 1) {
            v = ((n % 31) >= (k % 31)) ? W2[n*H + k] : 0.f;
        } else {
            v = (((n % 32) - 1) >= (k % 31)) ? W3[n*H + k] : 0.f;
        }
        e[i] = v;
    }
    uint4 r;
    r.x = pack2(e[0], e[1]);
    r.y = pack2(e[2], e[3]);
    r.z = pack2(e[4], e[5]);
    r.w = pack2(e[6], e[7]);
    g_wfrags[idx] = r;
}

// ---------------------------------------------------------------------------
// Main fused kernel
// ---------------------------------------------------------------------------
__device__ __forceinline__ void mma16816(float c[4], const unsigned a[4],
                                         unsigned b0, unsigned b1) {
    asm("mma.sync.aligned.m16n8k16.row.col.f32.f16.f16.f32 "
        "{%0,%1,%2,%3}, {%4,%5,%6,%7}, {%8,%9}, {%0,%1,%2,%3};"
        : "+f"(c[0]), "+f"(c[1]), "+f"(c[2]), "+f"(c[3])
        : "r"(a[0]), "r"(a[1]), "r"(a[2]), "r"(a[3]), "r"(b0), "r"(b1));
}

#define WARPS 4
#define NITER 8
#define ROWS_PER_CTA (WARPS*NITER*16)   // 512 samples per CTA

__global__ __launch_bounds__(128, 1)
void made_main(const float* __restrict__ x, const float* __restrict__ cond,
               const float* __restrict__ b1, const float* __restrict__ b2,
               const float* __restrict__ b3,
               float* __restrict__ out_u, float* __restrict__ out_ld) {
    extern __shared__ unsigned char smem_raw[];
    uint4* sW  = (uint4*)smem_raw;
    float* sb1 = (float*)(sW + NFRAG_TOT);
    float* sb2 = sb1 + H;
    float* sb3 = sb2 + H;

    for (int i = threadIdx.x; i < NFRAG_TOT; i += blockDim.x) sW[i] = g_wfrags[i];
    if (threadIdx.x < H)    { sb1[threadIdx.x] = b1[threadIdx.x];
                              sb2[threadIdx.x] = b2[threadIdx.x]; }
    if (threadIdx.x < 2*NI)   sb3[threadIdx.x] = b3[threadIdx.x];
    __syncthreads();

    const uint4* sWcat = sW;
    const uint4* sW2f  = sW + NFRAG_CAT;
    const uint4* sW3f  = sW + NFRAG_CAT + NFRAG_W2;

    int warp = threadIdx.x >> 5;
    int lane = threadIdx.x & 31;
    int g = lane >> 2, t = lane & 3;
    long long base = (long long)blockIdx.x * ROWS_PER_CTA;

    for (int it = 0; it < NITER; ++it) {
        long long m0 = base + (long long)(warp*NITER + it) * 16;
        const float* xb = x    + m0 * NI;
        const float* cb = cond + m0 * NC;

        // ---- Load A1 fragments (x | cond), stash fp32 x for epilogue ----
        unsigned a1[6][4];
        float xs[16];
#pragma unroll
        for (int kt = 0; kt < 2; ++kt)
#pragma unroll
            for (int p = 0; p < 4; ++p) {
                int row = g + (p & 1) * 8;
                int col = kt*16 + 2*t + (p >> 1) * 8;
                float2 v = *(const float2*)(xb + row*NI + col);
                a1[kt][p] = pack2(v.x, v.y);
                int nt = kt*2 + (p >> 1);
                xs[nt*4 + (p & 1)*2 + 0] = v.x;
                xs[nt*4 + (p & 1)*2 + 1] = v.y;
            }
#pragma unroll
        for (int kt = 2; kt < 6; ++kt)
#pragma unroll
            for (int p = 0; p < 4; ++p) {
                int row = g + (p & 1) * 8;
                int col = (kt-2)*16 + 2*t + (p >> 1) * 8;
                float2 v = *(const float2*)(cb + row*NC + col);
                a1[kt][p] = pack2(v.x, v.y);
            }

        // ---- Layer 1: h1 = [x|cond] @ Wcat + b1 ----
        float acc[16][4];
#pragma unroll
        for (int nt = 0; nt < 16; ++nt) {
            float f0 = sb1[nt*8 + 2*t], f1 = sb1[nt*8 + 2*t + 1];
            acc[nt][0] = f0; acc[nt][1] = f1; acc[nt][2] = f0; acc[nt][3] = f1;
        }
#pragma unroll
        for (int nt = 0; nt < 16; ++nt)
#pragma unroll
            for (int kp = 0; kp < 3; ++kp) {
                uint4 w = sWcat[(nt*3 + kp)*32 + lane];
                mma16816(acc[nt], a1[2*kp],   w.x, w.y);
                mma16816(acc[nt], a1[2*kp+1], w.z, w.w);
            }

        // ---- relu + repack accumulators as A fragments (layout identity) ----
        unsigned af[8][4];
#pragma unroll
        for (int kt = 0; kt < 8; ++kt) {
            af[kt][0] = pack2(fmaxf(acc[2*kt][0],  0.f), fmaxf(acc[2*kt][1],  0.f));
            af[kt][1] = pack2(fmaxf(acc[2*kt][2],  0.f), fmaxf(acc[2*kt][3],  0.f));
            af[kt][2] = pack2(fmaxf(acc[2*kt+1][0],0.f), fmaxf(acc[2*kt+1][1],0.f));
            af[kt][3] = pack2(fmaxf(acc[2*kt+1][2],0.f), fmaxf(acc[2*kt+1][3],0.f));
        }

        // ---- Layer 2: h2 = relu(h1 @ W2m + b2) ----
#pragma unroll
        for (int nt = 0; nt < 16; ++nt) {
            float f0 = sb2[nt*8 + 2*t], f1 = sb2[nt*8 + 2*t + 1];
            acc[nt][0] = f0; acc[nt][1] = f1; acc[nt][2] = f0; acc[nt][3] = f1;
        }
#pragma unroll
        for (int nt = 0; nt < 16; ++nt)
#pragma unroll
            for (int kp = 0; kp < 4; ++kp) {
                uint4 w = sW2f[(nt*4 + kp)*32 + lane];
                mma16816(acc[nt], af[2*kp],   w.x, w.y);
                mma16816(acc[nt], af[2*kp+1], w.z, w.w);
            }

#pragma unroll
        for (int kt = 0; kt < 8; ++kt) {
            unsigned v0 = pack2(fmaxf(acc[2*kt][0],  0.f), fmaxf(acc[2*kt][1],  0.f));
            unsigned v1 = pack2(fmaxf(acc[2*kt][2],  0.f), fmaxf(acc[2*kt][3],  0.f));
            unsigned v2 = pack2(fmaxf(acc[2*kt+1][0],0.f), fmaxf(acc[2*kt+1][1],0.f));
            unsigned v3 = pack2(fmaxf(acc[2*kt+1][2],0.f), fmaxf(acc[2*kt+1][3],0.f));
            af[kt][0] = v0; af[kt][1] = v1; af[kt][2] = v2; af[kt][3] = v3;
        }

        // ---- Layer 3: o = h2 @ W3m + b3  (N = 64, tiles 0..3 = m, 4..7 = a) ----
#pragma unroll
        for (int nt = 0; nt < 8; ++nt) {
            float f0 = sb3[nt*8 + 2*t], f1 = sb3[nt*8 + 2*t + 1];
            acc[nt][0] = f0; acc[nt][1] = f1; acc[nt][2] = f0; acc[nt][3] = f1;
        }
#pragma unroll
        for (int nt = 0; nt < 8; ++nt)
#pragma unroll
            for (int kp = 0; kp < 4; ++kp) {
                uint4 w = sW3f[(nt*4 + kp)*32 + lane];
                mma16816(acc[nt], af[2*kp],   w.x, w.y);
                mma16816(acc[nt], af[2*kp+1], w.z, w.w);
            }

        // ---- Epilogue: a=clip(a,-5,5); u=(x-m)*exp(-a); logdet=-sum(a) ----
        float sa0 = 0.f, sa1 = 0.f;
#pragma unroll
        for (int nt = 0; nt < 4; ++nt) {
            float a00 = fminf(fmaxf(acc[nt+4][0], -5.f), 5.f);
            float a01 = fminf(fmaxf(acc[nt+4][1], -5.f), 5.f);
            float a10 = fminf(fmaxf(acc[nt+4][2], -5.f), 5.f);
            float a11 = fminf(fmaxf(acc[nt+4][3], -5.f), 5.f);
            float u00 = (xs[nt*4+0] - acc[nt][0]) * __expf(-a00);
            float u01 = (xs[nt*4+1] - acc[nt][1]) * __expf(-a01);
            float u10 = (xs[nt*4+2] - acc[nt][2]) * __expf(-a10);
            float u11 = (xs[nt*4+3] - acc[nt][3]) * __expf(-a11);
            float2 w0; w0.x = u00; w0.y = u01;
            float2 w1; w1.x = u10; w1.y = u11;
            *(float2*)(out_u + (m0 + g    )*NI + nt*8 + 2*t) = w0;
            *(float2*)(out_u + (m0 + g + 8)*NI + nt*8 + 2*t) = w1;
            sa0 += a00 + a01;
            sa1 += a10 + a11;
        }
        sa0 += __shfl_xor_sync(0xffffffffu, sa0, 1);
        sa0 += __shfl_xor_sync(0xffffffffu, sa0, 2);
        sa1 += __shfl_xor_sync(0xffffffffu, sa1, 1);
        sa1 += __shfl_xor_sync(0xffffffffu, sa1, 2);
        if (t == 0) {
            out_ld[m0 + g]     = -sa0;
            out_ld[m0 + g + 8] = -sa1;
        }
    }
}

// ---------------------------------------------------------------------------
// Launch
// ---------------------------------------------------------------------------
extern "C" void kernel_launch(void* const* d_in, const int* in_sizes, int n_in,
                              void* d_out, int out_size) {
    const float* x    = (const float*)d_in[0];
    const float* cond = (const float*)d_in[1];
    const float* W1   = (const float*)d_in[2];
    const float* b1   = (const float*)d_in[3];
    const float* Wc   = (const float*)d_in[4];
    const float* W2   = (const float*)d_in[5];
    const float* b2   = (const float*)d_in[6];
    const float* W3   = (const float*)d_in[7];
    const float* b3   = (const float*)d_in[8];

    long long B = (long long)in_sizes[0] / NI;
    float* out_u  = (float*)d_out;
    float* out_ld = out_u + B * NI;

    // Pre-pack masked weights into fragment order (tiny kernel, same stream)
    made_prep<<<(NFRAG_TOT + 127) / 128, 128>>>(W1, Wc, W2, W3);

    cudaFuncSetAttribute(made_main, cudaFuncAttributeMaxDynamicSharedMemorySize,
                         SMEM_BYTES);

    int nCTA = (int)(B / ROWS_PER_CTA);
    made_main<<<nCTA, 128, SMEM_BYTES>>>(x, cond, b1, b2, b3, out_u, out_ld);
}

// round 7
// speedup vs baseline: 1.0156x; 1.0142x over previous
#include <cuda_runtime.h>
#include <cuda_fp16.h>
#include <cstdint>

// Problem constants (fixed by the dataset)
#define NI 32
#define H  128
#define NC 64

// Fragment-buffer geometry.
// Weights are stored as m16n8k16 B-fragments, K-pair-packed into uint4:
//   uint4 = { b0(kt=2kp), b1(kt=2kp), b0(kt=2kp+1), b1(kt=2kp+1) }
//   b0 = half2{ B[k0][n], B[k0+1][n] },  k0 = kt*16 + (lane%4)*2,  n = nt*8 + lane/4
//   b1 = same with k0+8
#define NFRAG_CAT (16*3*32)   // Wcat: K=96 (x|cond), N=128  -> 1536 uint4
#define NFRAG_W2  (16*4*32)   // W2:   K=128, N=128          -> 2048 uint4
#define NFRAG_W3  (8*4*32)    // W3:   K=128, N=64           -> 1024 uint4
#define NFRAG_TOT (NFRAG_CAT + NFRAG_W2 + NFRAG_W3)          // 4608 uint4 = 73728 B
#define SMEM_BYTES (NFRAG_TOT*16 + (H + H + 2*NI)*4)         // + biases = 75008 B

__device__ uint4 g_wfrags[NFRAG_TOT];

static __device__ __forceinline__ unsigned pack2(float a, float b) {
    __half2 h = __floats2half2_rn(a, b);
    return *reinterpret_cast<unsigned*>(&h);
}

// ---------------------------------------------------------------------------
// Pre-pack kernel: apply MADE masks, convert to f16, write fragment order.
// deg_hid[h] = h % 31 ; deg_in[i] = i ; deg_out[o] = o % 32 - 1
// Layer1 B[k][n]: k<32 -> W1[n][k] * (n%31 >= k) ; k>=32 -> Wc[n][k-32]
// Layer2 B[k][n]: W2[n][k] * (n%31 >= k%31)
// Layer3 B[k][n]: W3[n][k] * ((n%32 - 1) >= k%31)
// ---------------------------------------------------------------------------
__global__ void made_prep(const float* __restrict__ W1, const float* __restrict__ Wc,
                          const float* __restrict__ W2, const float* __restrict__ W3) {
    int idx = blockIdx.x * blockDim.x + threadIdx.x;
    if (idx >= NFRAG_TOT) return;
    int mat, base, KP;
    if (idx < NFRAG_CAT)                { mat = 0; base = idx;                       KP = 3; }
    else if (idx < NFRAG_CAT+NFRAG_W2)  { mat = 1; base = idx - NFRAG_CAT;           KP = 4; }
    else                                { mat = 2; base = idx - (NFRAG_CAT+NFRAG_W2); KP = 4; }
    int lane = base & 31;
    int kp   = (base >> 5) % KP;
    int nt   = (base >> 5) / KP;
    int t = lane & 3, g = lane >> 2;
    int n = nt * 8 + g;

    float e[8];
#pragma unroll
    for (int i = 0; i < 8; i++) {
        int regsel = i >> 1;                       // 0..3: b0/b1 of kt-even, b0/b1 of kt-odd
        int kt = 2*kp + (regsel >> 1);
        int k  = kt*16 + (regsel & 1)*8 + 2*t + (i & 1);
        float v;
        if (mat == 0) {
            if (k < NI) v = ((n % 31) >= k) ? W1[n*NI + k] : 0.f;
            else        v = Wc[n*NC + (k - NI)];
        } else if (mat == 1) {
            v = ((n % 31) >= (k % 31)) ? W2[n*H + k] : 0.f;
        } else {
            v = (((n % 32) - 1) >= (k % 31)) ? W3[n*H + k] : 0.f;
        }
        e[i] = v;
    }
    uint4 r;
    r.x = pack2(e[0], e[1]);
    r.y = pack2(e[2], e[3]);
    r.z = pack2(e[4], e[5]);
    r.w = pack2(e[6], e[7]);
    g_wfrags[idx] = r;
}

// ---------------------------------------------------------------------------
// Main fused kernel
// ---------------------------------------------------------------------------
__device__ __forceinline__ void mma16816(float c[4], const unsigned a[4],
                                         unsigned b0, unsigned b1) {
    asm("mma.sync.aligned.m16n8k16.row.col.f32.f16.f16.f32 "
        "{%0,%1,%2,%3}, {%4,%5,%6,%7}, {%8,%9}, {%0,%1,%2,%3};"
        : "+f"(c[0]), "+f"(c[1]), "+f"(c[2]), "+f"(c[3])
        : "r"(a[0]), "r"(a[1]), "r"(a[2]), "r"(a[3]), "r"(b0), "r"(b1));
}

#define WARPS 4
#define NITER 8
#define ROWS_PER_CTA (WARPS*NITER*16)   // 512 samples per CTA

__global__ __launch_bounds__(128, 1)
void made_main(const float* __restrict__ x, const float* __restrict__ cond,
               const float* __restrict__ b1, const float* __restrict__ b2,
               const float* __restrict__ b3,
               float* __restrict__ out_u, float* __restrict__ out_ld) {
    extern __shared__ unsigned char smem_raw[];
    uint4* sW  = (uint4*)smem_raw;
    float* sb1 = (float*)(sW + NFRAG_TOT);
    float* sb2 = sb1 + H;
    float* sb3 = sb2 + H;

    for (int i = threadIdx.x; i < NFRAG_TOT; i += blockDim.x) sW[i] = g_wfrags[i];
    if (threadIdx.x < H)    { sb1[threadIdx.x] = b1[threadIdx.x];
                              sb2[threadIdx.x] = b2[threadIdx.x]; }
    if (threadIdx.x < 2*NI)   sb3[threadIdx.x] = b3[threadIdx.x];
    __syncthreads();

    const uint4* sWcat = sW;
    const uint4* sW2f  = sW + NFRAG_CAT;
    const uint4* sW3f  = sW + NFRAG_CAT + NFRAG_W2;

    int warp = threadIdx.x >> 5;
    int lane = threadIdx.x & 31;
    int g = lane >> 2, t = lane & 3;
    long long base = (long long)blockIdx.x * ROWS_PER_CTA;

    for (int it = 0; it < NITER; ++it) {
        long long m0 = base + (long long)(warp*NITER + it) * 16;
        const float* xb = x    + m0 * NI;
        const float* cb = cond + m0 * NC;

        // ---- Load A1 fragments (x | cond), stash fp32 x for epilogue ----
        unsigned a1[6][4];
        float xs[16];
#pragma unroll
        for (int kt = 0; kt < 2; ++kt)
#pragma unroll
            for (int p = 0; p < 4; ++p) {
                int row = g + (p & 1) * 8;
                int col = kt*16 + 2*t + (p >> 1) * 8;
                float2 v = *(const float2*)(xb + row*NI + col);
                a1[kt][p] = pack2(v.x, v.y);
                int nt = kt*2 + (p >> 1);
                xs[nt*4 + (p & 1)*2 + 0] = v.x;
                xs[nt*4 + (p & 1)*2 + 1] = v.y;
            }
#pragma unroll
        for (int kt = 2; kt < 6; ++kt)
#pragma unroll
            for (int p = 0; p < 4; ++p) {
                int row = g + (p & 1) * 8;
                int col = (kt-2)*16 + 2*t + (p >> 1) * 8;
                float2 v = *(const float2*)(cb + row*NC + col);
                a1[kt][p] = pack2(v.x, v.y);
            }

        // ---- Layer 1: h1 = [x|cond] @ Wcat + b1 ----
        float acc[16][4];
#pragma unroll
        for (int nt = 0; nt < 16; ++nt) {
            float f0 = sb1[nt*8 + 2*t], f1 = sb1[nt*8 + 2*t + 1];
            acc[nt][0] = f0; acc[nt][1] = f1; acc[nt][2] = f0; acc[nt][3] = f1;
        }
#pragma unroll
        for (int nt = 0; nt < 16; ++nt)
#pragma unroll
            for (int kp = 0; kp < 3; ++kp) {
                uint4 w = sWcat[(nt*3 + kp)*32 + lane];
                mma16816(acc[nt], a1[2*kp],   w.x, w.y);
                mma16816(acc[nt], a1[2*kp+1], w.z, w.w);
            }

        // ---- relu + repack accumulators as A fragments (layout identity) ----
        unsigned af[8][4];
#pragma unroll
        for (int kt = 0; kt < 8; ++kt) {
            af[kt][0] = pack2(fmaxf(acc[2*kt][0],  0.f), fmaxf(acc[2*kt][1],  0.f));
            af[kt][1] = pack2(fmaxf(acc[2*kt][2],  0.f), fmaxf(acc[2*kt][3],  0.f));
            af[kt][2] = pack2(fmaxf(acc[2*kt+1][0],0.f), fmaxf(acc[2*kt+1][1],0.f));
            af[kt][3] = pack2(fmaxf(acc[2*kt+1][2],0.f), fmaxf(acc[2*kt+1][3],0.f));
        }

        // ---- Layer 2: h2 = relu(h1 @ W2m + b2) ----
#pragma unroll
        for (int nt = 0; nt < 16; ++nt) {
            float f0 = sb2[nt*8 + 2*t], f1 = sb2[nt*8 + 2*t + 1];
            acc[nt][0] = f0; acc[nt][1] = f1; acc[nt][2] = f0; acc[nt][3] = f1;
        }
#pragma unroll
        for (int nt = 0; nt < 16; ++nt)
#pragma unroll
            for (int kp = 0; kp < 4; ++kp) {
                uint4 w = sW2f[(nt*4 + kp)*32 + lane];
                mma16816(acc[nt], af[2*kp],   w.x, w.y);
                mma16816(acc[nt], af[2*kp+1], w.z, w.w);
            }

#pragma unroll
        for (int kt = 0; kt < 8; ++kt) {
            unsigned v0 = pack2(fmaxf(acc[2*kt][0],  0.f), fmaxf(acc[2*kt][1],  0.f));
            unsigned v1 = pack2(fmaxf(acc[2*kt][2],  0.f), fmaxf(acc[2*kt][3],  0.f));
            unsigned v2 = pack2(fmaxf(acc[2*kt+1][0],0.f), fmaxf(acc[2*kt+1][1],0.f));
            unsigned v3 = pack2(fmaxf(acc[2*kt+1][2],0.f), fmaxf(acc[2*kt+1][3],0.f));
            af[kt][0] = v0; af[kt][1] = v1; af[kt][2] = v2; af[kt][3] = v3;
        }

        // ---- Layer 3: o = h2 @ W3m + b3  (N = 64, tiles 0..3 = m, 4..7 = a) ----
#pragma unroll
        for (int nt = 0; nt < 8; ++nt) {
            float f0 = sb3[nt*8 + 2*t], f1 = sb3[nt*8 + 2*t + 1];
            acc[nt][0] = f0; acc[nt][1] = f1; acc[nt][2] = f0; acc[nt][3] = f1;
        }
#pragma unroll
        for (int nt = 0; nt < 8; ++nt)
#pragma unroll
            for (int kp = 0; kp < 4; ++kp) {
                uint4 w = sW3f[(nt*4 + kp)*32 + lane];
                mma16816(acc[nt], af[2*kp],   w.x, w.y);
                mma16816(acc[nt], af[2*kp+1], w.z, w.w);
            }

        // ---- Epilogue: a=clip(a,-5,5); u=(x-m)*exp(-a); logdet=-sum(a) ----
        float sa0 = 0.f, sa1 = 0.f;
#pragma unroll
        for (int nt = 0; nt < 4; ++nt) {
            float a00 = fminf(fmaxf(acc[nt+4][0], -5.f), 5.f);
            float a01 = fminf(fmaxf(acc[nt+4][1], -5.f), 5.f);
            float a10 = fminf(fmaxf(acc[nt+4][2], -5.f), 5.f);
            float a11 = fminf(fmaxf(acc[nt+4][3], -5.f), 5.f);
            float u00 = (xs[nt*4+0] - acc[nt][0]) * __expf(-a00);
            float u01 = (xs[nt*4+1] - acc[nt][1]) * __expf(-a01);
            float u10 = (xs[nt*4+2] - acc[nt][2]) * __expf(-a10);
            float u11 = (xs[nt*4+3] - acc[nt][3]) * __expf(-a11);
            float2 w0; w0.x = u00; w0.y = u01;
            float2 w1; w1.x = u10; w1.y = u11;
            *(float2*)(out_u + (m0 + g    )*NI + nt*8 + 2*t) = w0;
            *(float2*)(out_u + (m0 + g + 8)*NI + nt*8 + 2*t) = w1;
            sa0 += a00 + a01;
            sa1 += a10 + a11;
        }
        sa0 += __shfl_xor_sync(0xffffffffu, sa0, 1);
        sa0 += __shfl_xor_sync(0xffffffffu, sa0, 2);
        sa1 += __shfl_xor_sync(0xffffffffu, sa1, 1);
        sa1 += __shfl_xor_sync(0xffffffffu, sa1, 2);
        if (t == 0) {
            out_ld[m0 + g]     = -sa0;
            out_ld[m0 + g + 8] = -sa1;
        }
    }
}

// ---------------------------------------------------------------------------
// Launch
// ---------------------------------------------------------------------------
extern "C" void kernel_launch(void* const* d_in, const int* in_sizes, int n_in,
                              void* d_out, int out_size) {
    const float* x    = (const float*)d_in[0];
    const float* cond = (const float*)d_in[1];
    const float* W1   = (const float*)d_in[2];
    const float* b1   = (const float*)d_in[3];
    const float* Wc   = (const float*)d_in[4];
    const float* W2   = (const float*)d_in[5];
    const float* b2   = (const float*)d_in[6];
    const float* W3   = (const float*)d_in[7];
    const float* b3   = (const float*)d_in[8];

    long long B = (long long)in_sizes[0] / NI;
    float* out_u  = (float*)d_out;
    float* out_ld = out_u + B * NI;

    // Pre-pack masked weights into fragment order (tiny kernel, same stream)
    made_prep<<<(NFRAG_TOT + 127) / 128, 128>>>(W1, Wc, W2, W3);

    cudaFuncSetAttribute(made_main, cudaFuncAttributeMaxDynamicSharedMemorySize,
                         SMEM_BYTES);

    int nCTA = (int)(B / ROWS_PER_CTA);
    made_main<<<nCTA, 128, SMEM_BYTES>>>(x, cond, b1, b2, b3, out_u, out_ld);
}